// round 1
// baseline (speedup 1.0000x reference)
#include <cuda_runtime.h>
#include <math.h>

#define BB 32
#define NN 4096
#define DD 256
#define SS 16
#define KK 8
#define HH 128
#define NCHUNK 256
#define NBLK (NN / NCHUNK)      /* 16 blocks per batch */
#define PART (KK * SS + KK)     /* 136 partials per block */
#define TROWS 64
#define WPAD 258
#define SMEM_A ((TROWS * DD + 32 * WPAD) * 4)

// ---------------- device scratch (no allocations allowed) ----------------
__device__ __align__(16) float g_k[BB * NN * SS];        // 8 MB
__device__ __align__(16) float g_v[BB * NN * SS];        // 8 MB
__device__ __align__(16) float g_slots[BB * KK * SS];
__device__ __align__(16) float g_partial[BB * NBLK * PART];
__device__ __align__(16) float g_denom[BB * KK];

// Packed fp32x2 FMA (SASS FFMA2): 2x fp32 FMA throughput vs scalar FFMA.
__device__ __forceinline__ unsigned long long ffma2(unsigned long long a,
                                                    unsigned long long b,
                                                    unsigned long long c) {
    unsigned long long d;
    asm("fma.rn.f32x2 %0, %1, %2, %3;" : "=l"(d) : "l"(a), "l"(b), "l"(c));
    return d;
}
__device__ __forceinline__ float ull_lo(unsigned long long u) {
    return __uint_as_float((unsigned int)(u & 0xffffffffull));
}
__device__ __forceinline__ float ull_hi(unsigned long long u) {
    return __uint_as_float((unsigned int)(u >> 32));
}

// ---------------- Kernel A: LayerNorm(inputs) + project to k,v ----------------
// Grid: (B*N)/TROWS blocks, 256 threads. Each warp: 8 rows x 32 cols (16 k + 16 v).
__global__ void __launch_bounds__(256, 2) ln_proj_kernel(
    const float* __restrict__ x, const float* __restrict__ lnw,
    const float* __restrict__ lnb, const float* __restrict__ wk,
    const float* __restrict__ wvm) {
    extern __shared__ float sm[];
    float* xs = sm;                  // [TROWS][256] normalized rows
    float* ws = sm + TROWS * DD;     // [32][WPAD] weights (rows 0..15 = wk, 16..31 = wv)
    int tid = threadIdx.x, wid = tid >> 5, lane = tid & 31;
    int rowbase = blockIdx.x * TROWS;

    // stage weights (coalesced)
    for (int i = tid; i < 32 * DD; i += 256) {
        int c = i >> 8, d = i & 255;
        ws[c * WPAD + d] = (c < SS) ? wk[c * DD + d] : wvm[(c - SS) * DD + d];
    }

    int rb = wid * 8;
    const float4* lw4 = (const float4*)lnw;
    const float4* lb4 = (const float4*)lnb;
    float4 w0 = lw4[lane], w1 = lw4[lane + 32];
    float4 b0 = lb4[lane], b1 = lb4[lane + 32];
    for (int r = 0; r < 8; r++) {
        int row = rb + r;
        const float4* xr = (const float4*)(x + (size_t)(rowbase + row) * DD);
        float4 a = xr[lane], c = xr[lane + 32];
        float s = a.x + a.y + a.z + a.w + c.x + c.y + c.z + c.w;
        float q = a.x * a.x + a.y * a.y + a.z * a.z + a.w * a.w +
                  c.x * c.x + c.y * c.y + c.z * c.z + c.w * c.w;
#pragma unroll
        for (int o = 16; o; o >>= 1) {
            s += __shfl_xor_sync(0xffffffffu, s, o);
            q += __shfl_xor_sync(0xffffffffu, q, o);
        }
        float mu = s * (1.f / DD);
        float rs = rsqrtf(q * (1.f / DD) - mu * mu + 1e-5f);
        float4 o0, o1;
        o0.x = (a.x - mu) * rs * w0.x + b0.x;
        o0.y = (a.y - mu) * rs * w0.y + b0.y;
        o0.z = (a.z - mu) * rs * w0.z + b0.z;
        o0.w = (a.w - mu) * rs * w0.w + b0.w;
        o1.x = (c.x - mu) * rs * w1.x + b1.x;
        o1.y = (c.y - mu) * rs * w1.y + b1.y;
        o1.z = (c.z - mu) * rs * w1.z + b1.z;
        o1.w = (c.w - mu) * rs * w1.w + b1.w;
        ((float4*)(xs + row * DD))[lane] = o0;
        ((float4*)(xs + row * DD))[lane + 32] = o1;
    }
    __syncthreads();

    // 8 rows x 1 col(lane) over d, packed f32x2
    unsigned long long acc0[8], acc1[8];
#pragma unroll
    for (int r = 0; r < 8; r++) { acc0[r] = 0ull; acc1[r] = 0ull; }
    const float* wp = ws + lane * WPAD;
#pragma unroll 2
    for (int d4 = 0; d4 < DD / 4; d4++) {
        int d = d4 * 4;
        unsigned long long wv01 = *(const unsigned long long*)(wp + d);
        unsigned long long wv23 = *(const unsigned long long*)(wp + d + 2);
#pragma unroll
        for (int r = 0; r < 8; r++) {
            ulonglong2 xv = *(const ulonglong2*)(xs + (rb + r) * DD + d);
            acc0[r] = ffma2(xv.x, wv01, acc0[r]);
            acc1[r] = ffma2(xv.y, wv23, acc1[r]);
        }
    }
#pragma unroll
    for (int r = 0; r < 8; r++) {
        float v = (ull_lo(acc0[r]) + ull_hi(acc0[r])) +
                  (ull_lo(acc1[r]) + ull_hi(acc1[r]));
        int row = rowbase + rb + r;
        if (lane < SS) g_k[row * SS + lane] = v;
        else           g_v[row * SS + (lane - SS)] = v;
    }
}

// ---------------- Kernel B: per-iteration attention streaming pass ----------------
// Grid (NBLK, B), 256 threads. Computes q from slots, per-n softmax over slots,
// accumulates block-local numer[k][s], denom[k] -> g_partial. Last iter also
// writes raw (softmax+eps) attn to output (normalized later).
__global__ void __launch_bounds__(256) attn_kernel(
    const float* __restrict__ init_slots, const float* __restrict__ ln_s_w,
    const float* __restrict__ ln_s_b, const float* __restrict__ wq,
    float* __restrict__ out_attn, int iter, int last) {
    __shared__ float sm_xn[KK * SS];
    __shared__ float sm_q[KK * SS];
    __shared__ float sm_p[NCHUNK * KK];
    __shared__ float sm_v[NCHUNK * SS];
    int tid = threadIdx.x;
    int b = blockIdx.y, nb = blockIdx.x;
    const float* slots_in =
        (iter == 0) ? (init_slots + b * KK * SS) : (g_slots + b * KK * SS);

    if (tid < KK * SS) {
        int s = tid & 15;
        float v = slots_in[tid];
        float sum = v, sq = v * v;
#pragma unroll
        for (int o = 8; o; o >>= 1) {
            sum += __shfl_xor_sync(0xffffffffu, sum, o);
            sq += __shfl_xor_sync(0xffffffffu, sq, o);
        }
        float mu = sum * (1.f / SS);
        float rs = rsqrtf(sq * (1.f / SS) - mu * mu + 1e-5f);
        sm_xn[tid] = (v - mu) * rs * ln_s_w[s] + ln_s_b[s];
    }
    __syncthreads();
    if (tid < KK * SS) {
        int k = tid >> 4, t = tid & 15;
        float acc = 0.f;
#pragma unroll
        for (int s = 0; s < SS; s++) acc += sm_xn[k * SS + s] * wq[t * SS + s];
        sm_q[tid] = acc * 0.25f;  // scale = S^-0.5
    }
    // stage v tile
    {
        const float4* vsrc =
            (const float4*)(g_v + ((size_t)b * NN + (size_t)nb * NCHUNK) * SS);
        float4* vdst = (float4*)sm_v;
#pragma unroll
        for (int i = tid; i < NCHUNK * SS / 4; i += 256) vdst[i] = vsrc[i];
    }
    __syncthreads();

    // each thread: one n; softmax over 8 slots
    {
        int n = nb * NCHUNK + tid;
        const float4* kf4 = (const float4*)(g_k + ((size_t)b * NN + n) * SS);
        float4 k0 = kf4[0], k1 = kf4[1], k2 = kf4[2], k3 = kf4[3];
        float kf[16] = {k0.x, k0.y, k0.z, k0.w, k1.x, k1.y, k1.z, k1.w,
                        k2.x, k2.y, k2.z, k2.w, k3.x, k3.y, k3.z, k3.w};
        float lg[KK];
#pragma unroll
        for (int kk = 0; kk < KK; kk++) {
            float a = 0.f;
#pragma unroll
            for (int s = 0; s < SS; s++) a += sm_q[kk * SS + s] * kf[s];
            lg[kk] = a;
        }
        float m = lg[0];
#pragma unroll
        for (int kk = 1; kk < KK; kk++) m = fmaxf(m, lg[kk]);
        float sum = 0.f;
#pragma unroll
        for (int kk = 0; kk < KK; kk++) {
            lg[kk] = __expf(lg[kk] - m);
            sum += lg[kk];
        }
        float inv = 1.f / sum;
#pragma unroll
        for (int kk = 0; kk < KK; kk++) {
            float p = lg[kk] * inv + 1e-8f;
            sm_p[tid * KK + kk] = p;
            if (last) out_attn[((size_t)(b * KK + kk)) * NN + n] = p;
        }
    }
    __syncthreads();

    // block-local deterministic accumulation
    if (tid < 128) {
        int k = tid & 7, s = tid >> 3;
        float acc = 0.f;
#pragma unroll 4
        for (int n = 0; n < NCHUNK; n++) acc += sm_p[n * KK + k] * sm_v[n * SS + s];
        g_partial[((size_t)b * NBLK + nb) * PART + k * SS + s] = acc;
    } else if (tid < 128 + KK) {
        int k = tid - 128;
        float acc = 0.f;
#pragma unroll 4
        for (int n = 0; n < NCHUNK; n++) acc += sm_p[n * KK + k];
        g_partial[((size_t)b * NBLK + nb) * PART + 128 + k] = acc;
    }
}

// ---------------- Kernel C: reduce partials + GRU + LN + MLP ----------------
// Grid B, 256 threads. One block per batch.
__global__ void __launch_bounds__(256) update_kernel(
    const float* __restrict__ init_slots, const float* __restrict__ w_ih,
    const float* __restrict__ w_hh, const float* __restrict__ b_ih,
    const float* __restrict__ b_hh, const float* __restrict__ ln_m_w,
    const float* __restrict__ ln_m_b, const float* __restrict__ mlp_w1,
    const float* __restrict__ mlp_b1, const float* __restrict__ mlp_w2,
    const float* __restrict__ mlp_b2, float* __restrict__ out_slots, int iter,
    int last) {
    __shared__ float sm_upd[KK * SS];
    __shared__ float sm_h[KK * SS];
    __shared__ float sm_hp[KK * SS];
    __shared__ float sm_y[KK * SS];
    __shared__ float sm_h1[KK * HH];
    __shared__ float sm_den[KK];
    int tid = threadIdx.x;
    int b = blockIdx.x;
    const float* slots_in =
        (iter == 0) ? (init_slots + b * KK * SS) : (g_slots + b * KK * SS);

    if (tid < PART) {
        float s = 0.f;
#pragma unroll
        for (int j = 0; j < NBLK; j++)
            s += g_partial[((size_t)b * NBLK + j) * PART + tid];
        if (tid < KK * SS) {
            sm_upd[tid] = s;  // numerator for now
        } else {
            sm_den[tid - 128] = s;
            g_denom[b * KK + (tid - 128)] = s;
        }
    }
    if (tid < KK * SS) sm_hp[tid] = slots_in[tid];
    __syncthreads();
    if (tid < KK * SS) sm_upd[tid] = sm_upd[tid] / sm_den[tid >> 4];
    __syncthreads();

    // GRU cell (torch gate order [r, z, n])
    if (tid < KK * SS) {
        int k = tid >> 4, s = tid & 15;
        float ir = b_ih[s], iz = b_ih[SS + s], inn = b_ih[2 * SS + s];
        float hr = b_hh[s], hz = b_hh[SS + s], hn = b_hh[2 * SS + s];
#pragma unroll
        for (int t = 0; t < SS; t++) {
            float u = sm_upd[k * SS + t], hp = sm_hp[k * SS + t];
            ir += w_ih[s * SS + t] * u;
            iz += w_ih[(SS + s) * SS + t] * u;
            inn += w_ih[(2 * SS + s) * SS + t] * u;
            hr += w_hh[s * SS + t] * hp;
            hz += w_hh[(SS + s) * SS + t] * hp;
            hn += w_hh[(2 * SS + s) * SS + t] * hp;
        }
        float r = 1.f / (1.f + __expf(-(ir + hr)));
        float z = 1.f / (1.f + __expf(-(iz + hz)));
        float n = tanhf(inn + r * hn);
        sm_h[tid] = (1.f - z) * n + z * sm_hp[tid];
    }
    __syncthreads();
    // LayerNorm over S
    if (tid < KK * SS) {
        int s = tid & 15;
        float v = sm_h[tid];
        float sum = v, sq = v * v;
#pragma unroll
        for (int o = 8; o; o >>= 1) {
            sum += __shfl_xor_sync(0xffffffffu, sum, o);
            sq += __shfl_xor_sync(0xffffffffu, sq, o);
        }
        float mu = sum * (1.f / SS);
        float rs = rsqrtf(sq * (1.f / SS) - mu * mu + 1e-5f);
        sm_y[tid] = (v - mu) * rs * ln_m_w[s] + ln_m_b[s];
    }
    __syncthreads();
    // MLP layer 1 (relu)
    for (int i = tid; i < KK * HH; i += 256) {
        int k = i >> 7, hh = i & 127;
        float a = mlp_b1[hh];
#pragma unroll
        for (int s = 0; s < SS; s++) a += mlp_w1[hh * SS + s] * sm_y[k * SS + s];
        sm_h1[i] = fmaxf(a, 0.f);
    }
    __syncthreads();
    // MLP layer 2 + residual
    if (tid < KK * SS) {
        int k = tid >> 4, s = tid & 15;
        float a = mlp_b2[s];
#pragma unroll 8
        for (int h = 0; h < HH; h++) a += mlp_w2[s * HH + h] * sm_h1[k * HH + h];
        float ns = sm_h[tid] + a;
        g_slots[b * KK * SS + tid] = ns;
        if (last) out_slots[b * KK * SS + tid] = ns;
    }
}

// ---------------- Kernel D: normalize emitted attention ----------------
__global__ void __launch_bounds__(256) norm_attn_kernel(float* __restrict__ out_attn) {
    int i = blockIdx.x * 256 + threadIdx.x;
    out_attn[i] = out_attn[i] / g_denom[i >> 12];  // i>>12 == b*K + k (N = 4096)
}

// ---------------- launch ----------------
extern "C" void kernel_launch(void* const* d_in, const int* in_sizes, int n_in,
                              void* d_out, int out_size) {
    (void)in_sizes; (void)n_in; (void)out_size;
    const float* inputs     = (const float*)d_in[0];
    const float* init_slots = (const float*)d_in[1];
    const float* ln_in_w    = (const float*)d_in[2];
    const float* ln_in_b    = (const float*)d_in[3];
    const float* ln_s_w     = (const float*)d_in[4];
    const float* ln_s_b     = (const float*)d_in[5];
    const float* ln_m_w     = (const float*)d_in[6];
    const float* ln_m_b     = (const float*)d_in[7];
    const float* wq         = (const float*)d_in[8];
    const float* wk         = (const float*)d_in[9];
    const float* wv         = (const float*)d_in[10];
    const float* w_ih       = (const float*)d_in[11];
    const float* w_hh       = (const float*)d_in[12];
    const float* b_ih       = (const float*)d_in[13];
    const float* b_hh       = (const float*)d_in[14];
    const float* mlp_w1     = (const float*)d_in[15];
    const float* mlp_b1     = (const float*)d_in[16];
    const float* mlp_w2     = (const float*)d_in[17];
    const float* mlp_b2     = (const float*)d_in[18];
    float* out = (float*)d_out;
    float* out_slots = out;
    float* out_attn = out + BB * KK * SS;

    cudaFuncSetAttribute(ln_proj_kernel,
                         cudaFuncAttributeMaxDynamicSharedMemorySize, SMEM_A);
    ln_proj_kernel<<<(BB * NN) / TROWS, 256, SMEM_A>>>(inputs, ln_in_w, ln_in_b,
                                                       wk, wv);
    for (int it = 0; it < 3; it++) {
        int last = (it == 2) ? 1 : 0;
        dim3 gb(NBLK, BB);
        attn_kernel<<<gb, 256>>>(init_slots, ln_s_w, ln_s_b, wq, out_attn, it,
                                 last);
        update_kernel<<<BB, 256>>>(init_slots, w_ih, w_hh, b_ih, b_hh, ln_m_w,
                                   ln_m_b, mlp_w1, mlp_b1, mlp_w2, mlp_b2,
                                   out_slots, it, last);
    }
    norm_attn_kernel<<<(BB * KK * NN) / 256, 256>>>(out_attn);
}

// round 6
// speedup vs baseline: 1.0702x; 1.0702x over previous
#include <cuda_runtime.h>
#include <cuda_bf16.h>
#include <cstdint>
#include <math.h>

#define BB 32
#define NN 4096
#define DD 256
#define SS 16
#define KK 8
#define HH 128
#define NCHUNK 256
#define NBLK (NN / NCHUNK)      /* 16 chunks per batch */
#define PART (KK * SS + KK)     /* 136 partials per chunk */

// ---------------- device scratch ----------------
__device__ __align__(16) float g_k[BB * NN * SS];
__device__ __align__(16) float g_v[BB * NN * SS];
__device__ __align__(16) float g_slots[BB * KK * SS];
__device__ __align__(16) float g_q[BB * KK * SS];
__device__ __align__(16) float g_partial[BB * NBLK * PART];
__device__ __align__(16) float g_denom[BB * KK];

// ---------------- helpers ----------------
__device__ __forceinline__ unsigned long long ffma2(unsigned long long a,
                                                    unsigned long long b,
                                                    unsigned long long c) {
    unsigned long long d;
    asm("fma.rn.f32x2 %0, %1, %2, %3;" : "=l"(d) : "l"(a), "l"(b), "l"(c));
    return d;
}
__device__ __forceinline__ float ull_lo(unsigned long long u) {
    return __uint_as_float((unsigned int)(u & 0xffffffffull));
}
__device__ __forceinline__ float ull_hi(unsigned long long u) {
    return __uint_as_float((unsigned int)(u >> 32));
}

__device__ __forceinline__ void mma16816(float& c0, float& c1, float& c2,
                                         float& c3, uint32_t a0, uint32_t a1,
                                         uint32_t a2, uint32_t a3, uint32_t b0,
                                         uint32_t b1) {
    asm volatile(
        "mma.sync.aligned.m16n8k16.row.col.f32.bf16.bf16.f32 "
        "{%0,%1,%2,%3}, {%4,%5,%6,%7}, {%8,%9}, {%0,%1,%2,%3};"
        : "+f"(c0), "+f"(c1), "+f"(c2), "+f"(c3)
        : "r"(a0), "r"(a1), "r"(a2), "r"(a3), "r"(b0), "r"(b1));
}

// ---------------- Kernel A: LN(inputs) + bf16-split HMMA projection ---------
// 128 rows/CTA, 256 threads (8 warps x 16 rows), N=32 (16 k + 16 v), K=256.
// smem (halves, stride 264 = 528B -> bank-conflict-free fragment loads):
#define STRH 264
#define A_HI_B 0
#define A_LO_B (128 * STRH * 2)              /* 67584 */
#define B_HI_B (2 * 128 * STRH * 2)          /* 135168 */
#define B_LO_B (B_HI_B + 32 * STRH * 2)      /* 152064 */
#define SMEM_TC (B_LO_B + 32 * STRH * 2)     /* 168960 */

__global__ void __launch_bounds__(256, 1) ln_proj_tc(
    const float* __restrict__ x, const float* __restrict__ lnw,
    const float* __restrict__ lnb, const float* __restrict__ wk,
    const float* __restrict__ wvm) {
    extern __shared__ char smem[];
    int tid = threadIdx.x, wid = tid >> 5, lane = tid & 31;

    // ---- stage weights: row = tid>>3 (0..31), seg = tid&7 (32-col chunk)
    {
        int row = tid >> 3, seg = tid & 7;
        const float* src = (row < SS) ? (wk + row * DD + seg * 32)
                                      : (wvm + (row - SS) * DD + seg * 32);
        char* bh = smem + B_HI_B + row * (STRH * 2) + seg * 64;
        char* bl = smem + B_LO_B + row * (STRH * 2) + seg * 64;
#pragma unroll
        for (int i = 0; i < 32; i += 4) {
            float4 f = *(const float4*)(src + i);
            __nv_bfloat162 h0 = __floats2bfloat162_rn(f.x, f.y);
            __nv_bfloat162 h1 = __floats2bfloat162_rn(f.z, f.w);
            __nv_bfloat162 l0 = __floats2bfloat162_rn(f.x - __low2float(h0),
                                                      f.y - __high2float(h0));
            __nv_bfloat162 l1 = __floats2bfloat162_rn(f.z - __low2float(h1),
                                                      f.w - __high2float(h1));
            *(uint2*)(bh + i * 2) =
                make_uint2(*(uint32_t*)&h0, *(uint32_t*)&h1);
            *(uint2*)(bl + i * 2) =
                make_uint2(*(uint32_t*)&l0, *(uint32_t*)&l1);
        }
    }

    // ---- LN rows: warp w handles rows w*16 .. w*16+15
    {
        const float4* lw4 = (const float4*)lnw;
        const float4* lb4 = (const float4*)lnb;
        float4 w0 = lw4[lane], w1 = lw4[lane + 32];
        float4 b0 = lb4[lane], b1 = lb4[lane + 32];
        for (int rr = 0; rr < 16; rr++) {
            int r = wid * 16 + rr;
            size_t row = (size_t)blockIdx.x * 128 + r;
            const float4* xr = (const float4*)(x + row * DD);
            float4 a = xr[lane], c = xr[lane + 32];
            float s = a.x + a.y + a.z + a.w + c.x + c.y + c.z + c.w;
            float q = a.x * a.x + a.y * a.y + a.z * a.z + a.w * a.w +
                      c.x * c.x + c.y * c.y + c.z * c.z + c.w * c.w;
#pragma unroll
            for (int o = 16; o; o >>= 1) {
                s += __shfl_xor_sync(0xffffffffu, s, o);
                q += __shfl_xor_sync(0xffffffffu, q, o);
            }
            float mu = s * (1.f / DD);
            float rs = rsqrtf(q * (1.f / DD) - mu * mu + 1e-5f);
            float4 o0, o1;
            o0.x = (a.x - mu) * rs * w0.x + b0.x;
            o0.y = (a.y - mu) * rs * w0.y + b0.y;
            o0.z = (a.z - mu) * rs * w0.z + b0.z;
            o0.w = (a.w - mu) * rs * w0.w + b0.w;
            o1.x = (c.x - mu) * rs * w1.x + b1.x;
            o1.y = (c.y - mu) * rs * w1.y + b1.y;
            o1.z = (c.z - mu) * rs * w1.z + b1.z;
            o1.w = (c.w - mu) * rs * w1.w + b1.w;

            __nv_bfloat162 h0 = __floats2bfloat162_rn(o0.x, o0.y);
            __nv_bfloat162 h1 = __floats2bfloat162_rn(o0.z, o0.w);
            __nv_bfloat162 h2 = __floats2bfloat162_rn(o1.x, o1.y);
            __nv_bfloat162 h3 = __floats2bfloat162_rn(o1.z, o1.w);
            __nv_bfloat162 l0 = __floats2bfloat162_rn(o0.x - __low2float(h0),
                                                      o0.y - __high2float(h0));
            __nv_bfloat162 l1 = __floats2bfloat162_rn(o0.z - __low2float(h1),
                                                      o0.w - __high2float(h1));
            __nv_bfloat162 l2 = __floats2bfloat162_rn(o1.x - __low2float(h2),
                                                      o1.y - __high2float(h2));
            __nv_bfloat162 l3 = __floats2bfloat162_rn(o1.z - __low2float(h3),
                                                      o1.w - __high2float(h3));
            char* ah = smem + A_HI_B + r * (STRH * 2);
            char* al = smem + A_LO_B + r * (STRH * 2);
            *(uint2*)(ah + 8 * lane) = make_uint2(*(uint32_t*)&h0, *(uint32_t*)&h1);
            *(uint2*)(ah + 256 + 8 * lane) = make_uint2(*(uint32_t*)&h2, *(uint32_t*)&h3);
            *(uint2*)(al + 8 * lane) = make_uint2(*(uint32_t*)&l0, *(uint32_t*)&l1);
            *(uint2*)(al + 256 + 8 * lane) = make_uint2(*(uint32_t*)&l2, *(uint32_t*)&l3);
        }
    }
    __syncthreads();

    // ---- per-warp HMMA: 16 rows x 32 cols, K=256, 3 split terms
    {
        float acc[4][4];
#pragma unroll
        for (int t = 0; t < 4; t++)
#pragma unroll
            for (int j = 0; j < 4; j++) acc[t][j] = 0.f;

        int rbase = wid * 16;
        int arow0 = rbase + (lane >> 2);
        uint32_t koff = (lane & 3) * 2;  // halves
        const char* ah_base = smem + A_HI_B + arow0 * (STRH * 2);
        const char* al_base = smem + A_LO_B + arow0 * (STRH * 2);
        const char* bh_base = smem + B_HI_B + (lane >> 2) * (STRH * 2);
        const char* bl_base = smem + B_LO_B + (lane >> 2) * (STRH * 2);

#pragma unroll 4
        for (int ks = 0; ks < 16; ks++) {
            uint32_t kb = (ks * 16 + koff) * 2;  // byte offset in row
            uint32_t ah0 = *(const uint32_t*)(ah_base + kb);
            uint32_t ah1 = *(const uint32_t*)(ah_base + 8 * (STRH * 2) + kb);
            uint32_t ah2 = *(const uint32_t*)(ah_base + kb + 16);
            uint32_t ah3 = *(const uint32_t*)(ah_base + 8 * (STRH * 2) + kb + 16);
            uint32_t al0 = *(const uint32_t*)(al_base + kb);
            uint32_t al1 = *(const uint32_t*)(al_base + 8 * (STRH * 2) + kb);
            uint32_t al2 = *(const uint32_t*)(al_base + kb + 16);
            uint32_t al3 = *(const uint32_t*)(al_base + 8 * (STRH * 2) + kb + 16);
#pragma unroll
            for (int t = 0; t < 4; t++) {
                uint32_t bro = t * 8 * (STRH * 2);
                uint32_t bh0 = *(const uint32_t*)(bh_base + bro + kb);
                uint32_t bh1 = *(const uint32_t*)(bh_base + bro + kb + 16);
                uint32_t bl0 = *(const uint32_t*)(bl_base + bro + kb);
                uint32_t bl1 = *(const uint32_t*)(bl_base + bro + kb + 16);
                mma16816(acc[t][0], acc[t][1], acc[t][2], acc[t][3],
                         ah0, ah1, ah2, ah3, bh0, bh1);
                mma16816(acc[t][0], acc[t][1], acc[t][2], acc[t][3],
                         al0, al1, al2, al3, bh0, bh1);
                mma16816(acc[t][0], acc[t][1], acc[t][2], acc[t][3],
                         ah0, ah1, ah2, ah3, bl0, bl1);
            }
        }

        // epilogue: C fragment rows lane>>2, lane>>2+8; cols (lane&3)*2 (+1)
        size_t row0 = (size_t)blockIdx.x * 128 + rbase + (lane >> 2);
        int c0 = (lane & 3) * 2;
#pragma unroll
        for (int t = 0; t < 4; t++) {
            int n = t * 8 + c0;
            float* dst = (t < 2) ? g_k : g_v;
            int col = (t < 2) ? n : (n - 16);
            *(float2*)(dst + row0 * SS + col) = make_float2(acc[t][0], acc[t][1]);
            *(float2*)(dst + (row0 + 8) * SS + col) = make_float2(acc[t][2], acc[t][3]);
        }
    }
}

// ---------------- q generation (iter 0) -------------------------------------
__global__ void __launch_bounds__(128) q_init_kernel(
    const float* __restrict__ init_slots, const float* __restrict__ ln_s_w,
    const float* __restrict__ ln_s_b, const float* __restrict__ wq) {
    __shared__ float sm[KK * SS];
    int b = blockIdx.x, tid = threadIdx.x;
    int s = tid & 15;
    float v = init_slots[b * 128 + tid];
    float sum = v, sq = v * v;
#pragma unroll
    for (int o = 8; o; o >>= 1) {
        sum += __shfl_xor_sync(0xffffffffu, sum, o, 16);
        sq += __shfl_xor_sync(0xffffffffu, sq, o, 16);
    }
    float mu = sum * (1.f / SS);
    float rs = rsqrtf(sq * (1.f / SS) - mu * mu + 1e-5f);
    sm[tid] = (v - mu) * rs * ln_s_w[s] + ln_s_b[s];
    __syncthreads();
    int k = tid >> 4, t = tid & 15;
    float a = 0.f;
#pragma unroll
    for (int ss = 0; ss < SS; ss++) a += sm[k * SS + ss] * wq[t * SS + ss];
    g_q[b * 128 + tid] = a * 0.25f;
}

// ---------------- Kernel B: attention streaming pass ------------------------
__global__ void __launch_bounds__(256) attn_kernel(float* __restrict__ out_attn,
                                                   int last) {
    __shared__ float sm_q[KK * SS];
    __shared__ float sm_p[NCHUNK * KK];
    __shared__ float sm_v[NCHUNK * 18];
    __shared__ float2 sm_r[144];
    int tid = threadIdx.x;
    int b = blockIdx.y, nb = blockIdx.x;

    if (tid < 32) ((float4*)sm_q)[tid] = ((const float4*)(g_q + b * 128))[tid];
    {
        const unsigned long long* vs =
            (const unsigned long long*)(g_v + ((size_t)b * NN + (size_t)nb * NCHUNK) * SS);
#pragma unroll
        for (int i = tid; i < NCHUNK * 8; i += 256) {
            int n = i >> 3, j = i & 7;
            *(unsigned long long*)&sm_v[n * 18 + 2 * j] = vs[i];
        }
        sm_v[tid * 18 + 16] = 1.f;
        sm_v[tid * 18 + 17] = 0.f;
    }
    __syncthreads();

    {
        int n = nb * NCHUNK + tid;
        const float4* kf4 = (const float4*)(g_k + ((size_t)b * NN + n) * SS);
        float4 k0 = kf4[0], k1 = kf4[1], k2 = kf4[2], k3 = kf4[3];
        float kf[16] = {k0.x, k0.y, k0.z, k0.w, k1.x, k1.y, k1.z, k1.w,
                        k2.x, k2.y, k2.z, k2.w, k3.x, k3.y, k3.z, k3.w};
        float lg[KK];
#pragma unroll
        for (int kk = 0; kk < KK; kk++) {
            float a = 0.f;
#pragma unroll
            for (int s = 0; s < SS; s++) a += sm_q[kk * SS + s] * kf[s];
            lg[kk] = a;
        }
        float m = lg[0];
#pragma unroll
        for (int kk = 1; kk < KK; kk++) m = fmaxf(m, lg[kk]);
        float sum = 0.f;
#pragma unroll
        for (int kk = 0; kk < KK; kk++) {
            lg[kk] = __expf(lg[kk] - m);
            sum += lg[kk];
        }
        float inv = 1.f / sum;
#pragma unroll
        for (int kk = 0; kk < KK; kk++) {
            float p = lg[kk] * inv + 1e-8f;
            sm_p[tid * KK + kk] = p;
            if (last) out_attn[((size_t)(b * KK + kk)) * NN + n] = p;
        }
    }
    __syncthreads();

    // numer + denom reduce: 144 threads, f32x2, 2 halves of 128 n each
    if (tid < 144) {
        int half = (tid >= 72);
        int r = tid - half * 72;
        int k = r / 9, c = r % 9;
        unsigned long long acc = 0ull;
        int n0 = half * 128;
#pragma unroll 4
        for (int n = n0; n < n0 + 128; n++) {
            unsigned int pb = __float_as_uint(sm_p[n * KK + k]);
            unsigned long long p2 = ((unsigned long long)pb << 32) | pb;
            unsigned long long v2 = *(const unsigned long long*)&sm_v[n * 18 + 2 * c];
            acc = ffma2(p2, v2, acc);
        }
        sm_r[tid] = make_float2(ull_lo(acc), ull_hi(acc));
    }
    __syncthreads();
    if (tid < 72) {
        float2 A = sm_r[tid], B = sm_r[72 + tid];
        float lo = A.x + B.x, hi = A.y + B.y;
        int k = tid / 9, c = tid % 9;
        float* gp = g_partial + ((size_t)b * NBLK + nb) * PART;
        if (c < 8) {
            gp[k * SS + 2 * c] = lo;
            gp[k * SS + 2 * c + 1] = hi;
        } else {
            gp[128 + k] = lo;
        }
    }
}

// ---------------- Kernel C: reduce + GRU + LN + MLP + next-q ----------------
__global__ void __launch_bounds__(256) update_kernel(
    const float* __restrict__ init_slots, const float* __restrict__ w_ih,
    const float* __restrict__ w_hh, const float* __restrict__ b_ih,
    const float* __restrict__ b_hh, const float* __restrict__ ln_m_w,
    const float* __restrict__ ln_m_b, const float* __restrict__ mlp_w1,
    const float* __restrict__ mlp_b1, const float* __restrict__ mlp_w2,
    const float* __restrict__ mlp_b2, const float* __restrict__ ln_s_w,
    const float* __restrict__ ln_s_b, const float* __restrict__ wq,
    float* __restrict__ out_slots, int iter, int last) {
    __shared__ float sm_upd[KK * SS];
    __shared__ float sm_h[KK * SS];
    __shared__ float sm_hp[KK * SS];
    __shared__ float sm_y[KK * SS];
    __shared__ float sm_h1[KK * HH];
    __shared__ float sm_den[KK];
    int tid = threadIdx.x;
    int b = blockIdx.x;
    const float* slots_in =
        (iter == 0) ? (init_slots + b * KK * SS) : (g_slots + b * KK * SS);
    float ns = 0.f;

    if (tid < PART) {
        float s = 0.f;
#pragma unroll
        for (int j = 0; j < NBLK; j++)
            s += g_partial[((size_t)b * NBLK + j) * PART + tid];
        if (tid < KK * SS) {
            sm_upd[tid] = s;
        } else {
            sm_den[tid - 128] = s;
            g_denom[b * KK + (tid - 128)] = s;
        }
    }
    if (tid < KK * SS) sm_hp[tid] = slots_in[tid];
    __syncthreads();
    if (tid < KK * SS) sm_upd[tid] = sm_upd[tid] / sm_den[tid >> 4];
    __syncthreads();

    if (tid < KK * SS) {
        int k = tid >> 4, s = tid & 15;
        float ir = b_ih[s], iz = b_ih[SS + s], inn = b_ih[2 * SS + s];
        float hr = b_hh[s], hz = b_hh[SS + s], hn = b_hh[2 * SS + s];
#pragma unroll
        for (int t = 0; t < SS; t++) {
            float u = sm_upd[k * SS + t], hp = sm_hp[k * SS + t];
            ir += w_ih[s * SS + t] * u;
            iz += w_ih[(SS + s) * SS + t] * u;
            inn += w_ih[(2 * SS + s) * SS + t] * u;
            hr += w_hh[s * SS + t] * hp;
            hz += w_hh[(SS + s) * SS + t] * hp;
            hn += w_hh[(2 * SS + s) * SS + t] * hp;
        }
        float r = 1.f / (1.f + __expf(-(ir + hr)));
        float z = 1.f / (1.f + __expf(-(iz + hz)));
        float n = tanhf(inn + r * hn);
        sm_h[tid] = (1.f - z) * n + z * sm_hp[tid];
    }
    __syncthreads();
    if (tid < KK * SS) {
        int s = tid & 15;
        float v = sm_h[tid];
        float sum = v, sq = v * v;
#pragma unroll
        for (int o = 8; o; o >>= 1) {
            sum += __shfl_xor_sync(0xffffffffu, sum, o, 16);
            sq += __shfl_xor_sync(0xffffffffu, sq, o, 16);
        }
        float mu = sum * (1.f / SS);
        float rs = rsqrtf(sq * (1.f / SS) - mu * mu + 1e-5f);
        sm_y[tid] = (v - mu) * rs * ln_m_w[s] + ln_m_b[s];
    }
    __syncthreads();
    for (int i = tid; i < KK * HH; i += 256) {
        int k = i >> 7, hh = i & 127;
        float a = mlp_b1[hh];
#pragma unroll
        for (int s = 0; s < SS; s++) a += mlp_w1[hh * SS + s] * sm_y[k * SS + s];
        sm_h1[i] = fmaxf(a, 0.f);
    }
    __syncthreads();
    if (tid < KK * SS) {
        int k = tid >> 4, s = tid & 15;
        float a = mlp_b2[s];
#pragma unroll 8
        for (int h = 0; h < HH; h++) a += mlp_w2[s * HH + h] * sm_h1[k * HH + h];
        ns = sm_h[tid] + a;
        g_slots[b * KK * SS + tid] = ns;
        if (last) out_slots[b * KK * SS + tid] = ns;
    }

    if (!last) {
        __syncthreads();
        if (tid < KK * SS) {
            int s = tid & 15;
            float sum = ns, sq = ns * ns;
#pragma unroll
            for (int o = 8; o; o >>= 1) {
                sum += __shfl_xor_sync(0xffffffffu, sum, o, 16);
                sq += __shfl_xor_sync(0xffffffffu, sq, o, 16);
            }
            float mu = sum * (1.f / SS);
            float rs = rsqrtf(sq * (1.f / SS) - mu * mu + 1e-5f);
            sm_y[tid] = (ns - mu) * rs * ln_s_w[s] + ln_s_b[s];
        }
        __syncthreads();
        if (tid < KK * SS) {
            int k = tid >> 4, t = tid & 15;
            float a = 0.f;
#pragma unroll
            for (int s = 0; s < SS; s++) a += sm_y[k * SS + s] * wq[t * SS + s];
            g_q[b * 128 + tid] = a * 0.25f;
        }
    }
}

// ---------------- Kernel D: normalize emitted attention ----------------
__global__ void __launch_bounds__(256) norm_attn_kernel(float* __restrict__ out_attn) {
    int i = blockIdx.x * 256 + threadIdx.x;
    out_attn[i] = out_attn[i] / g_denom[i >> 12];
}

// ---------------- launch ----------------
extern "C" void kernel_launch(void* const* d_in, const int* in_sizes, int n_in,
                              void* d_out, int out_size) {
    (void)in_sizes; (void)n_in; (void)out_size;
    const float* inputs     = (const float*)d_in[0];
    const float* init_slots = (const float*)d_in[1];
    const float* ln_in_w    = (const float*)d_in[2];
    const float* ln_in_b    = (const float*)d_in[3];
    const float* ln_s_w     = (const float*)d_in[4];
    const float* ln_s_b     = (const float*)d_in[5];
    const float* ln_m_w     = (const float*)d_in[6];
    const float* ln_m_b     = (const float*)d_in[7];
    const float* wq         = (const float*)d_in[8];
    const float* wk         = (const float*)d_in[9];
    const float* wv         = (const float*)d_in[10];
    const float* w_ih       = (const float*)d_in[11];
    const float* w_hh       = (const float*)d_in[12];
    const float* b_ih       = (const float*)d_in[13];
    const float* b_hh       = (const float*)d_in[14];
    const float* mlp_w1     = (const float*)d_in[15];
    const float* mlp_b1     = (const float*)d_in[16];
    const float* mlp_w2     = (const float*)d_in[17];
    const float* mlp_b2     = (const float*)d_in[18];
    float* out = (float*)d_out;
    float* out_slots = out;
    float* out_attn = out + BB * KK * SS;

    cudaFuncSetAttribute(ln_proj_tc, cudaFuncAttributeMaxDynamicSharedMemorySize,
                         SMEM_TC);
    ln_proj_tc<<<(BB * NN) / 128, 256, SMEM_TC>>>(inputs, ln_in_w, ln_in_b, wk, wv);
    q_init_kernel<<<BB, 128>>>(init_slots, ln_s_w, ln_s_b, wq);
    for (int it = 0; it < 3; it++) {
        int last = (it == 2) ? 1 : 0;
        dim3 gb(NBLK, BB);
        attn_kernel<<<gb, 256>>>(out_attn, last);
        update_kernel<<<BB, 256>>>(init_slots, w_ih, w_hh, b_ih, b_hh, ln_m_w,
                                   ln_m_b, mlp_w1, mlp_b1, mlp_w2, mlp_b2,
                                   ln_s_w, ln_s_b, wq, out_slots, it, last);
    }
    norm_attn_kernel<<<(BB * KK * NN) / 256, 256>>>(out_attn);
}

// round 8
// speedup vs baseline: 1.3551x; 1.2662x over previous
#include <cuda_runtime.h>
#include <cuda_bf16.h>
#include <cstdint>
#include <math.h>

#define BB 32
#define NN 4096
#define DD 256
#define SS 16
#define KK 8
#define HH 128
#define NCHUNK 256
#define NBLK (NN / NCHUNK)      /* 16 chunks per batch */
#define PART (KK * SS + KK)     /* 136 partials per chunk */
#define NPROJ ((BB * NN) / 64)  /* 2048 projection blocks */

// ---------------- device scratch ----------------
__device__ __align__(16) float g_k[BB * NN * SS];
__device__ __align__(16) float g_v[BB * NN * SS];
__device__ __align__(16) float g_slots[BB * KK * SS];
__device__ __align__(16) float g_q[BB * KK * SS];
__device__ __align__(16) float g_partial[BB * NBLK * PART];
__device__ __align__(16) float g_denom[BB * KK];

// ---------------- helpers ----------------
typedef unsigned long long ull;
__device__ __forceinline__ ull ffma2(ull a, ull b, ull c) {
    ull d;
    asm("fma.rn.f32x2 %0, %1, %2, %3;" : "=l"(d) : "l"(a), "l"(b), "l"(c));
    return d;
}
__device__ __forceinline__ float ull_lo(ull u) {
    return __uint_as_float((unsigned int)(u & 0xffffffffull));
}
__device__ __forceinline__ float ull_hi(ull u) {
    return __uint_as_float((unsigned int)(u >> 32));
}

__device__ __forceinline__ void mma16816(float& c0, float& c1, float& c2,
                                         float& c3, uint32_t a0, uint32_t a1,
                                         uint32_t a2, uint32_t a3, uint32_t b0,
                                         uint32_t b1) {
    asm volatile(
        "mma.sync.aligned.m16n8k16.row.col.f32.bf16.bf16.f32 "
        "{%0,%1,%2,%3}, {%4,%5,%6,%7}, {%8,%9}, {%0,%1,%2,%3};"
        : "+f"(c0), "+f"(c1), "+f"(c2), "+f"(c3)
        : "r"(a0), "r"(a1), "r"(a2), "r"(a3), "r"(b0), "r"(b1));
}

// ---------------- Kernel A: LN(inputs) + bf16-split HMMA projection ---------
// 64 rows/CTA, 256 threads. Warp = (row-tile 16 x col-half 16), K=256.
// smem halves, row stride 264 halves (528B).
#define STRH 264
#define A_HI_B 0
#define A_LO_B (64 * STRH * 2)               /* 33792 */
#define B_HI_B (2 * 64 * STRH * 2)           /* 67584 */
#define B_LO_B (B_HI_B + 32 * STRH * 2)      /* 84480 */
#define SMEM_TC (B_LO_B + 32 * STRH * 2)     /* 101376 */

__global__ void __launch_bounds__(256) ln_proj_tc(
    const float* __restrict__ x, const float* __restrict__ lnw,
    const float* __restrict__ lnb, const float* __restrict__ wk,
    const float* __restrict__ wvm, const float* __restrict__ init_slots,
    const float* __restrict__ ln_s_w, const float* __restrict__ ln_s_b,
    const float* __restrict__ wq) {
    extern __shared__ char smem[];
    int tid = threadIdx.x, wid = tid >> 5, lane = tid & 31;

    // ---- fused q_init blocks ----
    if (blockIdx.x >= NPROJ) {
        __shared__ float smq[KK * SS];
        int b = blockIdx.x - NPROJ;
        if (tid < 128) {
            int s = tid & 15;
            float v = init_slots[b * 128 + tid];
            float sum = v, sq = v * v;
#pragma unroll
            for (int o = 8; o; o >>= 1) {
                sum += __shfl_xor_sync(0xffffffffu, sum, o, 16);
                sq += __shfl_xor_sync(0xffffffffu, sq, o, 16);
            }
            float mu = sum * (1.f / SS);
            float rs = rsqrtf(sq * (1.f / SS) - mu * mu + 1e-5f);
            smq[tid] = (v - mu) * rs * ln_s_w[s] + ln_s_b[s];
        }
        __syncthreads();
        if (tid < 128) {
            int k = tid >> 4, t = tid & 15;
            float a = 0.f;
#pragma unroll
            for (int ss = 0; ss < SS; ss++) a += smq[k * SS + ss] * wq[t * SS + ss];
            g_q[b * 128 + tid] = a * 0.25f;
        }
        return;
    }

    // ---- stage weights: row = tid>>3 (0..31), seg = tid&7 (32-col chunk)
    {
        int row = tid >> 3, seg = tid & 7;
        const float* src = (row < SS) ? (wk + row * DD + seg * 32)
                                      : (wvm + (row - SS) * DD + seg * 32);
        char* bh = smem + B_HI_B + row * (STRH * 2) + seg * 64;
        char* bl = smem + B_LO_B + row * (STRH * 2) + seg * 64;
#pragma unroll
        for (int i = 0; i < 32; i += 4) {
            float4 f = *(const float4*)(src + i);
            __nv_bfloat162 h0 = __floats2bfloat162_rn(f.x, f.y);
            __nv_bfloat162 h1 = __floats2bfloat162_rn(f.z, f.w);
            __nv_bfloat162 l0 = __floats2bfloat162_rn(f.x - __low2float(h0),
                                                      f.y - __high2float(h0));
            __nv_bfloat162 l1 = __floats2bfloat162_rn(f.z - __low2float(h1),
                                                      f.w - __high2float(h1));
            *(uint2*)(bh + i * 2) = make_uint2(*(uint32_t*)&h0, *(uint32_t*)&h1);
            *(uint2*)(bl + i * 2) = make_uint2(*(uint32_t*)&l0, *(uint32_t*)&l1);
        }
    }

    // ---- LN: warp w handles rows w*8 .. w*8+7
    {
        const float4* lw4 = (const float4*)lnw;
        const float4* lb4 = (const float4*)lnb;
        float4 w0 = lw4[lane], w1 = lw4[lane + 32];
        float4 b0 = lb4[lane], b1 = lb4[lane + 32];
#pragma unroll 2
        for (int rr = 0; rr < 8; rr++) {
            int r = wid * 8 + rr;
            size_t row = (size_t)blockIdx.x * 64 + r;
            const float4* xr = (const float4*)(x + row * DD);
            float4 a = xr[lane], c = xr[lane + 32];
            float s = a.x + a.y + a.z + a.w + c.x + c.y + c.z + c.w;
            float q = a.x * a.x + a.y * a.y + a.z * a.z + a.w * a.w +
                      c.x * c.x + c.y * c.y + c.z * c.z + c.w * c.w;
#pragma unroll
            for (int o = 16; o; o >>= 1) {
                s += __shfl_xor_sync(0xffffffffu, s, o);
                q += __shfl_xor_sync(0xffffffffu, q, o);
            }
            float mu = s * (1.f / DD);
            float rs = rsqrtf(q * (1.f / DD) - mu * mu + 1e-5f);
            float4 o0, o1;
            o0.x = (a.x - mu) * rs * w0.x + b0.x;
            o0.y = (a.y - mu) * rs * w0.y + b0.y;
            o0.z = (a.z - mu) * rs * w0.z + b0.z;
            o0.w = (a.w - mu) * rs * w0.w + b0.w;
            o1.x = (c.x - mu) * rs * w1.x + b1.x;
            o1.y = (c.y - mu) * rs * w1.y + b1.y;
            o1.z = (c.z - mu) * rs * w1.z + b1.z;
            o1.w = (c.w - mu) * rs * w1.w + b1.w;

            __nv_bfloat162 h0 = __floats2bfloat162_rn(o0.x, o0.y);
            __nv_bfloat162 h1 = __floats2bfloat162_rn(o0.z, o0.w);
            __nv_bfloat162 h2 = __floats2bfloat162_rn(o1.x, o1.y);
            __nv_bfloat162 h3 = __floats2bfloat162_rn(o1.z, o1.w);
            __nv_bfloat162 l0 = __floats2bfloat162_rn(o0.x - __low2float(h0),
                                                      o0.y - __high2float(h0));
            __nv_bfloat162 l1 = __floats2bfloat162_rn(o0.z - __low2float(h1),
                                                      o0.w - __high2float(h1));
            __nv_bfloat162 l2 = __floats2bfloat162_rn(o1.x - __low2float(h2),
                                                      o1.y - __high2float(h2));
            __nv_bfloat162 l3 = __floats2bfloat162_rn(o1.z - __low2float(h3),
                                                      o1.w - __high2float(h3));
            char* ah = smem + A_HI_B + r * (STRH * 2);
            char* al = smem + A_LO_B + r * (STRH * 2);
            *(uint2*)(ah + 8 * lane) = make_uint2(*(uint32_t*)&h0, *(uint32_t*)&h1);
            *(uint2*)(ah + 256 + 8 * lane) = make_uint2(*(uint32_t*)&h2, *(uint32_t*)&h3);
            *(uint2*)(al + 8 * lane) = make_uint2(*(uint32_t*)&l0, *(uint32_t*)&l1);
            *(uint2*)(al + 256 + 8 * lane) = make_uint2(*(uint32_t*)&l2, *(uint32_t*)&l3);
        }
    }
    __syncthreads();

    // ---- per-warp HMMA: rtile = wid>>1 (16 rows), chalf = wid&1 (16 cols)
    {
        float acc[2][4];
#pragma unroll
        for (int t = 0; t < 2; t++)
#pragma unroll
            for (int j = 0; j < 4; j++) acc[t][j] = 0.f;

        int rtile = wid >> 1, chalf = wid & 1;
        int arow0 = rtile * 16 + (lane >> 2);
        uint32_t koff = (lane & 3) * 2;
        const char* ah_base = smem + A_HI_B + arow0 * (STRH * 2);
        const char* al_base = smem + A_LO_B + arow0 * (STRH * 2);
        const char* bh_base =
            smem + B_HI_B + (chalf * 16 + (lane >> 2)) * (STRH * 2);
        const char* bl_base =
            smem + B_LO_B + (chalf * 16 + (lane >> 2)) * (STRH * 2);

#pragma unroll 4
        for (int ks = 0; ks < 16; ks++) {
            uint32_t kb = (ks * 16 + koff) * 2;
            uint32_t ah0 = *(const uint32_t*)(ah_base + kb);
            uint32_t ah1 = *(const uint32_t*)(ah_base + 8 * (STRH * 2) + kb);
            uint32_t ah2 = *(const uint32_t*)(ah_base + kb + 16);
            uint32_t ah3 = *(const uint32_t*)(ah_base + 8 * (STRH * 2) + kb + 16);
            uint32_t al0 = *(const uint32_t*)(al_base + kb);
            uint32_t al1 = *(const uint32_t*)(al_base + 8 * (STRH * 2) + kb);
            uint32_t al2 = *(const uint32_t*)(al_base + kb + 16);
            uint32_t al3 = *(const uint32_t*)(al_base + 8 * (STRH * 2) + kb + 16);
#pragma unroll
            for (int t = 0; t < 2; t++) {
                uint32_t bro = t * 8 * (STRH * 2);
                uint32_t bh0 = *(const uint32_t*)(bh_base + bro + kb);
                uint32_t bh1 = *(const uint32_t*)(bh_base + bro + kb + 16);
                uint32_t bl0 = *(const uint32_t*)(bl_base + bro + kb);
                uint32_t bl1 = *(const uint32_t*)(bl_base + bro + kb + 16);
                mma16816(acc[t][0], acc[t][1], acc[t][2], acc[t][3],
                         ah0, ah1, ah2, ah3, bh0, bh1);
                mma16816(acc[t][0], acc[t][1], acc[t][2], acc[t][3],
                         al0, al1, al2, al3, bh0, bh1);
                mma16816(acc[t][0], acc[t][1], acc[t][2], acc[t][3],
                         ah0, ah1, ah2, ah3, bl0, bl1);
            }
        }

        size_t row0 = (size_t)blockIdx.x * 64 + rtile * 16 + (lane >> 2);
        int c0 = (lane & 3) * 2;
        float* dst = chalf ? g_v : g_k;
#pragma unroll
        for (int t = 0; t < 2; t++) {
            int col = t * 8 + c0;
            *(float2*)(dst + row0 * SS + col) = make_float2(acc[t][0], acc[t][1]);
            *(float2*)(dst + (row0 + 8) * SS + col) = make_float2(acc[t][2], acc[t][3]);
        }
    }
}

// ---------------- Kernel B: attention streaming pass ------------------------
__global__ void __launch_bounds__(256) attn_kernel(float* __restrict__ out_attn,
                                                   int last) {
    __shared__ float sm_q[KK * SS];
    __shared__ ull sm_p2[NCHUNK * KK];
    __shared__ float sm_v[NCHUNK * 18];
    __shared__ float2 sm_r[144];
    int tid = threadIdx.x;
    int b = blockIdx.y, nb = blockIdx.x;

    if (tid < 32) ((float4*)sm_q)[tid] = ((const float4*)(g_q + b * 128))[tid];
    {
        const ull* vs =
            (const ull*)(g_v + ((size_t)b * NN + (size_t)nb * NCHUNK) * SS);
#pragma unroll
        for (int i = tid; i < NCHUNK * 8; i += 256) {
            int n = i >> 3, j = i & 7;
            *(ull*)&sm_v[n * 18 + 2 * j] = vs[i];
        }
        sm_v[tid * 18 + 16] = 1.f;
        sm_v[tid * 18 + 17] = 0.f;
    }
    __syncthreads();

    {
        int n = nb * NCHUNK + tid;
        union { float4 f4[4]; ull u[8]; } kf;
        const float4* kf4 = (const float4*)(g_k + ((size_t)b * NN + n) * SS);
        kf.f4[0] = kf4[0]; kf.f4[1] = kf4[1];
        kf.f4[2] = kf4[2]; kf.f4[3] = kf4[3];
        const ull* q2 = (const ull*)sm_q;
        float lg[KK];
#pragma unroll
        for (int kk = 0; kk < KK; kk++) {
            ull acc = 0ull;
#pragma unroll
            for (int p = 0; p < 8; p++) acc = ffma2(q2[kk * 8 + p], kf.u[p], acc);
            lg[kk] = ull_lo(acc) + ull_hi(acc);
        }
        float m = lg[0];
#pragma unroll
        for (int kk = 1; kk < KK; kk++) m = fmaxf(m, lg[kk]);
        float sum = 0.f;
#pragma unroll
        for (int kk = 0; kk < KK; kk++) {
            lg[kk] = __expf(lg[kk] - m);
            sum += lg[kk];
        }
        float inv = 1.f / sum;
#pragma unroll
        for (int kk = 0; kk < KK; kk++) {
            float p = lg[kk] * inv + 1e-8f;
            unsigned int pb = __float_as_uint(p);
            sm_p2[tid * KK + kk] = ((ull)pb << 32) | pb;
            if (last) out_attn[((size_t)(b * KK + kk)) * NN + n] = p;
        }
    }
    __syncthreads();

    // numer + denom reduce: 144 threads, f32x2, 2 halves of 128 n each
    if (tid < 144) {
        int half = (tid >= 72);
        int r = tid - half * 72;
        int k = r / 9, c = r % 9;
        ull a0 = 0ull, a1 = 0ull;
        int n0 = half * 128;
#pragma unroll 4
        for (int n = n0; n < n0 + 128; n += 2) {
            a0 = ffma2(sm_p2[n * KK + k], *(const ull*)&sm_v[n * 18 + 2 * c], a0);
            a1 = ffma2(sm_p2[(n + 1) * KK + k],
                       *(const ull*)&sm_v[(n + 1) * 18 + 2 * c], a1);
        }
        sm_r[tid] = make_float2(ull_lo(a0) + ull_lo(a1), ull_hi(a0) + ull_hi(a1));
    }
    __syncthreads();
    if (tid < 72) {
        float2 A = sm_r[tid], B = sm_r[72 + tid];
        float lo = A.x + B.x, hi = A.y + B.y;
        int k = tid / 9, c = tid % 9;
        float* gp = g_partial + ((size_t)b * NBLK + nb) * PART;
        if (c < 8) {
            gp[k * SS + 2 * c] = lo;
            gp[k * SS + 2 * c + 1] = hi;
        } else {
            gp[128 + k] = lo;
        }
    }
}

// ---------------- Kernel C: per-(b,k) reduce + GRU + LN + MLP + next-q ------
__global__ void __launch_bounds__(128) update_kernel(
    const float* __restrict__ init_slots, const float* __restrict__ w_ih,
    const float* __restrict__ w_hh, const float* __restrict__ b_ih,
    const float* __restrict__ b_hh, const float* __restrict__ ln_m_w,
    const float* __restrict__ ln_m_b, const float* __restrict__ mlp_w1,
    const float* __restrict__ mlp_b1, const float* __restrict__ mlp_w2,
    const float* __restrict__ mlp_b2, const float* __restrict__ ln_s_w,
    const float* __restrict__ ln_s_b, const float* __restrict__ wq,
    float* __restrict__ out_slots, int iter, int last) {
    __shared__ float s_num[16], s_upd[16], s_hp[16], s_h[16], s_y[16];
    __shared__ float s_h1[128], s_ns[16];
    __shared__ float s_den;
    int t = threadIdx.x;
    int b = blockIdx.x >> 3, k = blockIdx.x & 7;
    const float* slots_in =
        (iter == 0) ? (init_slots + b * 128) : (g_slots + b * 128);

    if (t < 17) {
        float s = 0.f;
        int off = (t < 16) ? (k * SS + t) : (128 + k);
#pragma unroll
        for (int j = 0; j < NBLK; j++)
            s += g_partial[((size_t)(b * NBLK + j)) * PART + off];
        if (t < 16) s_num[t] = s;
        else { s_den = s; g_denom[b * KK + k] = s; }
    }
    if (t < 16) s_hp[t] = slots_in[k * SS + t];
    __syncthreads();
    if (t < 16) s_upd[t] = s_num[t] / s_den;
    __syncthreads();

    // GRU (torch gate order [r,z,n])
    if (t < 16) {
        float ir = b_ih[t], iz = b_ih[SS + t], inn = b_ih[2 * SS + t];
        float hr = b_hh[t], hz = b_hh[SS + t], hn = b_hh[2 * SS + t];
#pragma unroll
        for (int tt = 0; tt < SS; tt++) {
            float u = s_upd[tt], hp = s_hp[tt];
            ir += w_ih[t * SS + tt] * u;
            iz += w_ih[(SS + t) * SS + tt] * u;
            inn += w_ih[(2 * SS + t) * SS + tt] * u;
            hr += w_hh[t * SS + tt] * hp;
            hz += w_hh[(SS + t) * SS + tt] * hp;
            hn += w_hh[(2 * SS + t) * SS + tt] * hp;
        }
        float r = 1.f / (1.f + __expf(-(ir + hr)));
        float z = 1.f / (1.f + __expf(-(iz + hz)));
        float n = tanhf(inn + r * hn);
        float h = (1.f - z) * n + z * s_hp[t];
        s_h[t] = h;
        // LayerNorm over S (lanes 0..15 of warp 0)
        float sum = h, sq = h * h;
#pragma unroll
        for (int o = 8; o; o >>= 1) {
            sum += __shfl_xor_sync(0xffffu, sum, o, 16);
            sq += __shfl_xor_sync(0xffffu, sq, o, 16);
        }
        float mu = sum * (1.f / SS);
        float rs = rsqrtf(sq * (1.f / SS) - mu * mu + 1e-5f);
        s_y[t] = (h - mu) * rs * ln_m_w[t] + ln_m_b[t];
    }
    __syncthreads();

    // MLP1: one hidden unit per thread
    {
        float a = mlp_b1[t];
#pragma unroll
        for (int s = 0; s < SS; s++) a += mlp_w1[t * SS + s] * s_y[s];
        s_h1[t] = fmaxf(a, 0.f);
    }
    __syncthreads();

    // MLP2: 16 outputs x 8 threads, width-8 shfl reduce
    {
        int s = t >> 3, part = t & 7;
        float a = 0.f;
#pragma unroll
        for (int j = 0; j < 16; j++)
            a += mlp_w2[s * HH + part * 16 + j] * s_h1[part * 16 + j];
        a += __shfl_xor_sync(0xffffffffu, a, 4, 8);
        a += __shfl_xor_sync(0xffffffffu, a, 2, 8);
        a += __shfl_xor_sync(0xffffffffu, a, 1, 8);
        if (part == 0) {
            float ns = s_h[s] + mlp_b2[s] + a;
            s_ns[s] = ns;
            g_slots[b * 128 + k * SS + s] = ns;
            if (last) out_slots[b * 128 + k * SS + s] = ns;
        }
    }
    __syncthreads();

    if (!last && t < 16) {
        float v = s_ns[t];
        float sum = v, sq = v * v;
#pragma unroll
        for (int o = 8; o; o >>= 1) {
            sum += __shfl_xor_sync(0xffffu, sum, o, 16);
            sq += __shfl_xor_sync(0xffffu, sq, o, 16);
        }
        float mu = sum * (1.f / SS);
        float rs = rsqrtf(sq * (1.f / SS) - mu * mu + 1e-5f);
        s_y[t] = (v - mu) * rs * ln_s_w[t] + ln_s_b[t];
        __syncwarp(0xffffu);
        float a = 0.f;
#pragma unroll
        for (int s = 0; s < SS; s++) a += s_y[s] * wq[t * SS + s];
        g_q[b * 128 + k * SS + t] = a * 0.25f;
    }
}

// ---------------- Kernel D: normalize emitted attention (float4) ------------
__global__ void __launch_bounds__(256) norm_attn_kernel(float4* __restrict__ out_attn) {
    int i = blockIdx.x * 256 + threadIdx.x;   // 262144 float4s
    float4 p = out_attn[i];
    float inv = 1.f / g_denom[i >> 10];       // 1024 float4 per (b,k) row
    p.x *= inv; p.y *= inv; p.z *= inv; p.w *= inv;
    out_attn[i] = p;
}

// ---------------- launch ----------------
extern "C" void kernel_launch(void* const* d_in, const int* in_sizes, int n_in,
                              void* d_out, int out_size) {
    (void)in_sizes; (void)n_in; (void)out_size;
    const float* inputs     = (const float*)d_in[0];
    const float* init_slots = (const float*)d_in[1];
    const float* ln_in_w    = (const float*)d_in[2];
    const float* ln_in_b    = (const float*)d_in[3];
    const float* ln_s_w     = (const float*)d_in[4];
    const float* ln_s_b     = (const float*)d_in[5];
    const float* ln_m_w     = (const float*)d_in[6];
    const float* ln_m_b     = (const float*)d_in[7];
    const float* wq         = (const float*)d_in[8];
    const float* wk         = (const float*)d_in[9];
    const float* wv         = (const float*)d_in[10];
    const float* w_ih       = (const float*)d_in[11];
    const float* w_hh       = (const float*)d_in[12];
    const float* b_ih       = (const float*)d_in[13];
    const float* b_hh       = (const float*)d_in[14];
    const float* mlp_w1     = (const float*)d_in[15];
    const float* mlp_b1     = (const float*)d_in[16];
    const float* mlp_w2     = (const float*)d_in[17];
    const float* mlp_b2     = (const float*)d_in[18];
    float* out = (float*)d_out;
    float* out_slots = out;
    float* out_attn = out + BB * KK * SS;

    cudaFuncSetAttribute(ln_proj_tc, cudaFuncAttributeMaxDynamicSharedMemorySize,
                         SMEM_TC);
    ln_proj_tc<<<NPROJ + BB, 256, SMEM_TC>>>(inputs, ln_in_w, ln_in_b, wk, wv,
                                             init_slots, ln_s_w, ln_s_b, wq);
    for (int it = 0; it < 3; it++) {
        int last = (it == 2) ? 1 : 0;
        dim3 gb(NBLK, BB);
        attn_kernel<<<gb, 256>>>(out_attn, last);
        update_kernel<<<BB * KK, 128>>>(init_slots, w_ih, w_hh, b_ih, b_hh,
                                        ln_m_w, ln_m_b, mlp_w1, mlp_b1, mlp_w2,
                                        mlp_b2, ln_s_w, ln_s_b, wq, out_slots,
                                        it, last);
    }
    norm_attn_kernel<<<(BB * KK * NN) / 1024, 256>>>((float4*)out_attn);
}